// round 3
// baseline (speedup 1.0000x reference)
#include <cuda_runtime.h>
#include <cuda_bf16.h>
#include <cstdint>

#define DEVINL __device__ __forceinline__

// ---------------- problem constants ----------------
constexpr int F  = 128;      // feature dim (K)
constexpr int B  = 256;      // batch
constexpr int R  = 512;      // J*B GEMM rows
constexpr int Q  = 65536;    // queue size
constexpr int TN = 256;      // queue rows per CTA chunk
constexpr int QG = Q / TN;   // 256 q groups
constexpr int SSTR = 272;    // padded bf16 row stride in smem (256 data + 16 pad)
constexpr float INV_T = 10.0f;
constexpr float LOG2E = 1.4426950408889634f;
constexpr float CEXP  = INV_T * LOG2E;   // exp(10*d) = 2^(CEXP*d)

constexpr int SMEM_BYTES = TN * SSTR;    // 69632

// ---------------- scratch (no allocs allowed) ----------------
__device__ float g_pos[R];
__device__ float g_sq[QG * R];

// ---------------- helpers ----------------
DEVINL float ex2f(float x) { float y; asm("ex2.approx.ftz.f32 %0, %1;" : "=f"(y) : "f"(x)); return y; }

DEVINL uint32_t cvt2(float a, float b) {
    __nv_bfloat162 h = __floats2bfloat162_rn(a, b);   // .x = a (low), .y = b (high)
    return *reinterpret_cast<uint32_t*>(&h);
}

// mma.sync m16n8k16 row.col bf16 -> f32 accumulate (HMMA on sm_10x; no 'a' features)
DEVINL void mma16816(float* d, const uint32_t* a, uint32_t b0, uint32_t b1) {
    asm volatile(
        "mma.sync.aligned.m16n8k16.row.col.f32.bf16.bf16.f32 "
        "{%0,%1,%2,%3}, {%4,%5,%6,%7}, {%8,%9}, {%0,%1,%2,%3};"
        : "+f"(d[0]), "+f"(d[1]), "+f"(d[2]), "+f"(d[3])
        : "r"(a[0]), "r"(a[1]), "r"(a[2]), "r"(a[3]), "r"(b0), "r"(b1));
}

// ================= kernel 1: pos (exact fp32) =================
__global__ void prep_kernel(const float* __restrict__ V, const float* __restrict__ L) {
    int t = threadIdx.x;           // 512 threads, 1 CTA
    if (t >= R) return;
    int b = t & (B - 1);
    const float4* v = (const float4*)(V + (size_t)t * F);
    const float4* l = (const float4*)(L + (size_t)b * F);
    float acc = 0.f;
#pragma unroll
    for (int i = 0; i < F / 4; i++) {
        float4 a = v[i], c = l[i];
        acc += a.x * c.x + a.y * c.y + a.z * c.z + a.w * c.w;
    }
    g_pos[t] = acc * INV_T;
}

// ================= kernel 2: HMMA GEMM + fused exp row-sum =================
// grid = (2, QG). CTA covers rows [cg*256, cg*256+256) x queue [qg*TN, qg*TN+TN).
__global__ void __launch_bounds__(256, 2)
gemm_exp_kernel(const float* __restrict__ V, const float* __restrict__ queue) {
    extern __shared__ char smem[];   // bf16 queue chunk: TN rows x SSTR bytes

    const int tid  = threadIdx.x;
    const int w    = tid >> 5;
    const int lane = tid & 31;
    const int g    = lane >> 2;      // 0..7
    const int tg   = lane & 3;       // 0..3
    const int cg   = blockIdx.x;     // 0..1  (row half)
    const int qg   = blockIdx.y;     // 0..QG-1

    // ---- A fragments: warp rows [cg*256 + w*32, +32), resident in registers ----
    uint32_t a[2][8][4];
    {
        const float* Ab = V + (size_t)(cg * 256 + w * 32) * F;
#pragma unroll
        for (int m = 0; m < 2; m++) {
#pragma unroll
            for (int k = 0; k < 8; k++) {
                int r0 = m * 16 + g, r1 = r0 + 8;
                int c0 = k * 16 + 2 * tg, c1 = c0 + 8;
                float2 f;
                f = *(const float2*)(Ab + r0 * F + c0); a[m][k][0] = cvt2(f.x, f.y);
                f = *(const float2*)(Ab + r1 * F + c0); a[m][k][1] = cvt2(f.x, f.y);
                f = *(const float2*)(Ab + r0 * F + c1); a[m][k][2] = cvt2(f.x, f.y);
                f = *(const float2*)(Ab + r1 * F + c1); a[m][k][3] = cvt2(f.x, f.y);
            }
        }
    }

    // ---- stage queue chunk fp32 -> bf16 into padded smem ----
    {
        const float* Qb = queue + (size_t)qg * TN * F;
#pragma unroll 4
        for (int i = tid; i < TN * F / 4; i += 256) {
            int row = i >> 5;              // 32 float4 per row
            int c   = (i & 31) << 2;
            float4 v4 = *(const float4*)(Qb + row * F + c);
            uint2 st;
            st.x = cvt2(v4.x, v4.y);
            st.y = cvt2(v4.z, v4.w);
            *reinterpret_cast<uint2*>(smem + row * SSTR + c * 2) = st;
        }
    }
    __syncthreads();

    // ---- main loop: 32 n8 tiles, K=128 as 8 HMMAs per m-block ----
    float s[2][2] = {{0.f, 0.f}, {0.f, 0.f}};
#pragma unroll 1
    for (int n8 = 0; n8 < TN / 8; n8++) {
        const char* bp = smem + (n8 * 8 + g) * SSTR + tg * 4;
        float acc0[4] = {0.f, 0.f, 0.f, 0.f};
        float acc1[4] = {0.f, 0.f, 0.f, 0.f};
#pragma unroll
        for (int k = 0; k < 8; k++) {
            uint32_t b0 = *(const uint32_t*)(bp + k * 32);
            uint32_t b1 = *(const uint32_t*)(bp + k * 32 + 16);
            mma16816(acc0, a[0][k], b0, b1);
            mma16816(acc1, a[1][k], b0, b1);
        }
        s[0][0] += ex2f(acc0[0] * CEXP) + ex2f(acc0[1] * CEXP);
        s[0][1] += ex2f(acc0[2] * CEXP) + ex2f(acc0[3] * CEXP);
        s[1][0] += ex2f(acc1[0] * CEXP) + ex2f(acc1[1] * CEXP);
        s[1][1] += ex2f(acc1[2] * CEXP) + ex2f(acc1[3] * CEXP);
    }

    // ---- quad reduce over tg (n sub-columns), deterministic store ----
#pragma unroll
    for (int m = 0; m < 2; m++)
#pragma unroll
        for (int i = 0; i < 2; i++) {
            s[m][i] += __shfl_xor_sync(0xFFFFFFFFu, s[m][i], 1);
            s[m][i] += __shfl_xor_sync(0xFFFFFFFFu, s[m][i], 2);
        }
    if (tg == 0) {
        int rowbase = cg * 256 + w * 32;
        float* dst = g_sq + (size_t)qg * R + rowbase;
        dst[g]      = s[0][0];
        dst[g + 8]  = s[0][1];
        dst[g + 16] = s[1][0];
        dst[g + 24] = s[1][1];
    }
}

// ================= kernel 3: reduce + loss =================
__global__ void finalize_kernel(float* __restrict__ out) {
    __shared__ float sh[R];
    int t = threadIdx.x;          // 512 threads
    float pos = g_pos[t];
    sh[t] = ex2f(pos * LOG2E);    // exp(pos)
    __syncthreads();
    // per-j sums (two independent 256-halves)
    for (int off = 128; off > 0; off >>= 1) {
        if ((t & 255) < off) sh[t] += sh[t + off];
        __syncthreads();
    }
    float spos = sh[(t >> 8) << 8];
    __syncthreads();
    // reduce S_q over QG q-group partials (coalesced, deterministic)
    float sq = 0.f;
    for (int i = 0; i < QG; i++) sq += g_sq[(size_t)i * R + t];
    sh[t] = pos - logf(spos + sq);
    __syncthreads();
    for (int off = 256; off > 0; off >>= 1) {
        if (t < off) sh[t] += sh[t + off];
        __syncthreads();
    }
    if (t == 0) out[0] = -sh[0] / (float)B;
}

// ================= launch =================
extern "C" void kernel_launch(void* const* d_in, const int* in_sizes, int n_in,
                              void* d_out, int out_size) {
    (void)in_sizes; (void)n_in; (void)out_size;
    const float* V     = (const float*)d_in[0];
    const float* L     = (const float*)d_in[1];
    const float* queue = (const float*)d_in[2];
    float* out = (float*)d_out;

    cudaFuncSetAttribute(gemm_exp_kernel, cudaFuncAttributeMaxDynamicSharedMemorySize, SMEM_BYTES);

    prep_kernel<<<1, 512>>>(V, L);
    gemm_exp_kernel<<<dim3(2, QG), 256, SMEM_BYTES>>>(V, queue);
    finalize_kernel<<<1, 512>>>(out);
}